// round 13
// baseline (speedup 1.0000x reference)
#include <cuda_runtime.h>
#include <cuda_bf16.h>
#include <cstdint>

#define BSZ 512
#define DIM 128
#define MARGIN 0.2f
#define APB 4                 // anchors per block
#define NBLK (BSZ / APB)      // 128 blocks
#define NTHR 512              // 16 warps; each warp computes 32 rows
#define SD_STRIDE 520         // floats per sd row (bank-staggered for 4-lane STS)

// Scratch (no allocations anywhere)
__device__ float g_psum[BSZ];
__device__ int   g_pcnt[BSZ];
__device__ int   g_ctr;       // zero-init; last block resets -> replay-safe

typedef unsigned long long ull;

// ---- packed f32x2 helpers (Blackwell) -------------------------------------
__device__ __forceinline__ ull add2(ull a, ull b) {
    ull r; asm("add.rn.f32x2 %0, %1, %2;" : "=l"(r) : "l"(a), "l"(b)); return r;
}
__device__ __forceinline__ ull fma2(ull a, ull b, ull c) {
    ull r; asm("fma.rn.f32x2 %0, %1, %2, %3;" : "=l"(r) : "l"(a), "l"(b), "l"(c)); return r;
}
__device__ __forceinline__ float sum2(ull v) {
    float lo, hi;
    asm("mov.b64 {%0, %1}, %2;" : "=f"(lo), "=f"(hi) : "l"(v));
    return lo + hi;
}
__device__ __forceinline__ ull pack2(float x, float y) {
    ull r; asm("mov.b64 %0, {%1, %2};" : "=l"(r) : "f"(x), "f"(y)); return r;
}

// ---------------------------------------------------------------------------
// ONE fused kernel, no smem staging for B.
//  Phase 1: lane l owns dims [4l,4l+4) of every row. Warp loads one B row per
//           LDG.128 (coalesced); 4 NEGATED anchor slices live in registers.
//           diff = packed add of negated anchor; sum((a-b)^2) accumulated in
//           2 packed accs per anchor, folded across lanes with 6 shuffles ->
//           lanes 0..3 write sqrt-if-positive into sd. Zero barriers.
//  Phase 2: warp-per-row mining (ballot masks, shuffle prefix neg-rank,
//           warp-uniform early-exit window scan; reference quirks kept).
//  Phase 3: atomic-counter last-block deterministic finalize.
// ---------------------------------------------------------------------------
__global__ __launch_bounds__(NTHR, 1)
void fused_kernel(const float* __restrict__ emb,
                  const int* __restrict__ labels,
                  float* __restrict__ out) {
    __shared__ __align__(16) float sd[APB][SD_STRIDE];
    __shared__ int sLast;

    const int tid  = threadIdx.x;
    const int warp = tid >> 5;
    const int lane = tid & 31;
    const int i0   = blockIdx.x * APB;

    // ---- anchor fragments in registers: NEGATED dims 4l..4l+3 of each ----
    ull af0[APB], af1[APB];
    #pragma unroll
    for (int a = 0; a < APB; a++) {
        const float4 v = __ldg((const float4*)(emb + (size_t)(i0 + a) * DIM) + lane);
        af0[a] = pack2(-v.x, -v.y);
        af1[a] = pack2(-v.z, -v.w);
    }

    // ---- phase 1: 32 rows per warp, 1 LDG.128 per row per lane ----
    const int jbase = warp * 32;
    #pragma unroll 4
    for (int r = 0; r < 32; r++) {
        const int j = jbase + r;
        const float4 b = __ldg((const float4*)(emb + (size_t)j * DIM) + lane);
        const ull b0 = pack2(b.x, b.y);
        const ull b1 = pack2(b.z, b.w);

        float part0, part1, part2, part3;
        {
            ull u, acc;
            u = add2(b0, af0[0]); acc = fma2(u, u, 0ull);
            u = add2(b1, af1[0]); acc = fma2(u, u, acc);
            part0 = sum2(acc);
            u = add2(b0, af0[1]); acc = fma2(u, u, 0ull);
            u = add2(b1, af1[1]); acc = fma2(u, u, acc);
            part1 = sum2(acc);
            u = add2(b0, af0[2]); acc = fma2(u, u, 0ull);
            u = add2(b1, af1[2]); acc = fma2(u, u, acc);
            part2 = sum2(acc);
            u = add2(b0, af0[3]); acc = fma2(u, u, 0ull);
            u = add2(b1, af1[3]); acc = fma2(u, u, acc);
            part3 = sum2(acc);
        }

        // multi-value fold: 4 partials -> 1 per lane-group, then xor tree.
        // step1 (xor 1): even lanes keep anchors {0,1}, odd keep {2,3}
        const float u1 = __shfl_xor_sync(0xffffffffu, (lane & 1) ? part0 : part2, 1);
        const float n0 = ((lane & 1) ? part2 : part0) + u1;
        const float u2 = __shfl_xor_sync(0xffffffffu, (lane & 1) ? part1 : part3, 1);
        const float n1 = ((lane & 1) ? part3 : part1) + u2;
        // step2 (xor 2): bit1=0 keeps n0, bit1=1 keeps n1
        const float u3 = __shfl_xor_sync(0xffffffffu, (lane & 2) ? n0 : n1, 2);
        float m = ((lane & 2) ? n1 : n0) + u3;
        // steps 3-5: plain xor reduction within anchor-groups
        m += __shfl_xor_sync(0xffffffffu, m, 4);
        m += __shfl_xor_sync(0xffffffffu, m, 8);
        m += __shfl_xor_sync(0xffffffffu, m, 16);

        if (lane < 4) {
            const int a = ((lane & 1) << 1) | (lane >> 1);  // lane->anchor map
            sd[a][j] = m > 0.f ? sqrtf(m) : 0.f;
        }
    }
    __syncthreads();

    // ---- phase 2: warps 0..3 mine row i = i0 + warp ----
    if (warp < APB) {
        const int w = warp;
        const int i = i0 + w;
        const int li = __ldg(labels + i);

        // neg ballot words; lane q holds word q
        unsigned myneg = 0;
        #pragma unroll
        for (int q = 0; q < 16; q++) {
            const int lab = __ldg(labels + q * 32 + lane);
            const unsigned b = __ballot_sync(0xffffffffu, lab != li);
            if (lane == q) myneg = b;
        }

        // positive & (p>i) words; valid-pair count
        unsigned myposgt = 0;
        if (lane < 16) {
            const int r = i - lane * 32;
            const unsigned gt = (r < 0) ? 0xffffffffu
                              : (r >= 31 ? 0u : (0xffffffffu << (r + 1)));
            myposgt = (~myneg) & gt;
        }
        const int cnt = __reduce_add_sync(0xffffffffu,
                                          (lane < 16) ? __popc(myposgt) : 0);

        // exclusive prefix of per-word negative counts (shuffle scan)
        int spf;
        {
            const int nc = (lane < 16) ? __popc(myneg) : 0;
            int incl = nc;
            #pragma unroll
            for (int d = 1; d < 16; d <<= 1) {
                const int tt = __shfl_up_sync(0xffffffffu, incl, d);
                if (lane >= d) incl += tt;
            }
            spf = incl - nc;
        }

        // fallback j0 = first negative index (argmax over all-False == 0)
        int j0 = 0;
        {
            const unsigned negany =
                __ballot_sync(0xffffffffu, lane < 16 && myneg != 0);
            if (negany) {
                const int c0 = __ffs(negany) - 1;
                const unsigned w0 = __shfl_sync(0xffffffffu, myneg, c0);
                j0 = c0 * 32 + (__ffs(w0) - 1);
            }
        }
        const float dfb = sd[w][j0];

        unsigned pmask16 = __ballot_sync(0xffffffffu, lane < 16 && myposgt != 0);

        float psum = 0.f;
        while (pmask16) {                 // words containing positives
            const int c = __ffs(pmask16) - 1;
            pmask16 &= pmask16 - 1;
            unsigned pm = __shfl_sync(0xffffffffu, myposgt, c);  // uniform
            while (pm) {
                const int b = __ffs(pm) - 1;
                pm &= pm - 1;
                const int p = c * 32 + b;
                const float dap = sd[w][p];
                const float hi  = dap + MARGIN;
                int minj = -1;
                #pragma unroll 1
                for (int q = 0; q < 16; q++) {     // warp-uniform early exit
                    const unsigned nw = __shfl_sync(0xffffffffu, myneg, q);
                    const float dj = sd[w][q * 32 + lane];
                    const bool hit = ((nw >> lane) & 1u) && dj > dap && dj < hi;
                    const unsigned bm = __ballot_sync(0xffffffffu, hit);
                    if (bm) { minj = q * 32 + (__ffs(bm) - 1); break; }
                }
                float dan;
                if (minj >= 0) {
                    const int mc = minj >> 5, mb = minj & 31;
                    const int base = __shfl_sync(0xffffffffu, spf, mc);
                    const unsigned nw = __shfl_sync(0xffffffffu, myneg, mc);
                    const int rank = base + __popc(nw & ((1u << mb) - 1u));
                    dan = sd[w][rank];    // reference quirk: index by neg-rank
                } else {
                    dan = dfb;
                }
                const float v = fmaf(dap, dap, MARGIN) - dan * dan;
                psum += v > 0.f ? v : 0.f;   // uniform across lanes
            }
        }

        if (lane == 0) {
            g_psum[i] = psum;
            g_pcnt[i] = cnt;
            __threadfence();
        }
    }
    __syncthreads();

    // ---- phase 3: last-block deterministic finalize ----
    if (tid == 0) {
        const int prev = atomicAdd(&g_ctr, 1);
        sLast = (prev == NBLK - 1) ? 1 : 0;
    }
    __syncthreads();

    if (sLast) {
        __threadfence();
        __shared__ float rs[256];
        __shared__ int   rc[256];
        if (tid < 256) {
            rs[tid] = g_psum[tid] + g_psum[tid + 256];
            rc[tid] = g_pcnt[tid] + g_pcnt[tid + 256];
        }
        __syncthreads();
        #pragma unroll
        for (int s = 128; s > 0; s >>= 1) {
            if (tid < s) { rs[tid] += rs[tid + s]; rc[tid] += rc[tid + s]; }
            __syncthreads();
        }
        if (tid == 0) {
            out[0] = rs[0] / (float)rc[0];
            g_ctr  = 0;                    // reset for next graph replay
        }
    }
}

// ---------------------------------------------------------------------------
extern "C" void kernel_launch(void* const* d_in, const int* in_sizes, int n_in,
                              void* d_out, int out_size) {
    const float* emb    = (const float*)d_in[0];
    const int*   labels = (const int*)d_in[1];
    float*       out    = (float*)d_out;

    fused_kernel<<<NBLK, NTHR>>>(emb, labels, out);
}